// round 1
// baseline (speedup 1.0000x reference)
#include <cuda_runtime.h>
#include <math.h>

#define NREF 50000
#define NQ   25000
#define NE   400000
#define C0   128
#define C1   256
#define C2   256
#define BN_EPS 1e-5f

// ---------------- scratch (static device globals; no allocations) ----------------
__device__ float d_tmpF[NREF * C0];   // ref_feat @ Wf0 (pre-BN)
__device__ float d_tmpS[NQ * C0];     // query_feat @ Ws0 (pre-BN)
__device__ float d_x0[NQ * C0];       // relu(query_f + query_skip)
__device__ float d_tmp1[NQ * C1];     // x0 @ W1 + b1 (pre-BN)
__device__ float d_tmp2[NQ * C2];     // bnrelu(tmp1) @ W2 + b2 (pre-BN)

__device__ float d_sumF[C0], d_sqF[C0], d_sumS[C0], d_sqS[C0];
__device__ float d_sum1[C1], d_sq1[C1], d_sum2[C2], d_sq2[C2];
__device__ float d_aF[C0], d_bF[C0], d_aS[C0], d_bS[C0];
__device__ float d_a1[C1], d_b1n[C1], d_a2[C2], d_b2n[C2];

__device__ int   d_cnt[NQ];
__device__ int   d_off[NQ + 1];
__device__ int   d_cur[NQ];
__device__ int   d_er[NE];
__device__ float d_ew[NE];

// ---------------- zero init ----------------
__global__ void zero_k() {
    int i = blockIdx.x * blockDim.x + threadIdx.x;
    for (int t = i; t < NQ; t += gridDim.x * blockDim.x) d_cnt[t] = 0;
    if (i < C0) { d_sumF[i] = 0.f; d_sqF[i] = 0.f; d_sumS[i] = 0.f; d_sqS[i] = 0.f; }
    if (i < C1) { d_sum1[i] = 0.f; d_sq1[i] = 0.f; }
    if (i < C2) { d_sum2[i] = 0.f; d_sq2[i] = 0.f; }
}

// ---------------- SGEMM with per-channel stats, optional bias, optional A-side BN+ReLU ----------------
// C[M,N] = f(A)[M,K] @ B[K,N] (+bias);  f(v, k) = relu(v*aT[k]+bT[k]) if aT else v
// Tiles: BM=128, BN=64, BK=16, 256 threads, 8x4 per thread.
__global__ void __launch_bounds__(256) sgemm_stats(
    const float* __restrict__ A, const float* __restrict__ B,
    const float* __restrict__ bias,
    const float* __restrict__ aT, const float* __restrict__ bT,
    float* __restrict__ C,
    float* __restrict__ gsum, float* __restrict__ gsq,
    int M, int K, int N)
{
    __shared__ float As[16][128];
    __shared__ float Bs[16][64];
    __shared__ float sSum[64], sSq[64];

    const int tid  = threadIdx.x;
    const int row0 = blockIdx.y * 128;
    const int col0 = blockIdx.x * 64;

    if (tid < 64) { sSum[tid] = 0.f; sSq[tid] = 0.f; }

    const int ty = tid >> 4;       // 0..15  (row group: rows ty*8..ty*8+7)
    const int tx = tid & 15;       // 0..15  (col group: cols tx*4..tx*4+3)

    float acc[8][4];
#pragma unroll
    for (int i = 0; i < 8; i++)
#pragma unroll
        for (int j = 0; j < 4; j++) acc[i][j] = 0.f;

    const int aRow = tid >> 1;           // 0..127
    const int aK   = (tid & 1) * 4;      // 0 or 4
    const int bK   = tid >> 4;           // 0..15
    const int bN   = (tid & 15) * 4;

    for (int k0 = 0; k0 < K; k0 += 16) {
        // load A tile (transposed into As[k][row]); rows guarded, K multiple of 16
#pragma unroll
        for (int h = 0; h < 2; h++) {
            int kk = aK + 8 * h;
            float4 v = make_float4(0.f, 0.f, 0.f, 0.f);
            int gr = row0 + aRow;
            if (gr < M) v = *(const float4*)(A + (size_t)gr * K + k0 + kk);
            if (aT) {
                int kb = k0 + kk;
                v.x = fmaxf(fmaf(v.x, aT[kb + 0], bT[kb + 0]), 0.f);
                v.y = fmaxf(fmaf(v.y, aT[kb + 1], bT[kb + 1]), 0.f);
                v.z = fmaxf(fmaf(v.z, aT[kb + 2], bT[kb + 2]), 0.f);
                v.w = fmaxf(fmaf(v.w, aT[kb + 3], bT[kb + 3]), 0.f);
            }
            As[kk + 0][aRow] = v.x;
            As[kk + 1][aRow] = v.y;
            As[kk + 2][aRow] = v.z;
            As[kk + 3][aRow] = v.w;
        }
        // load B tile (N multiple of 64, K multiple of 16 -> unguarded)
        {
            float4 v = *(const float4*)(B + (size_t)(k0 + bK) * N + col0 + bN);
            *(float4*)&Bs[bK][bN] = v;
        }
        __syncthreads();

#pragma unroll
        for (int kk = 0; kk < 16; kk++) {
            float a[8], b[4];
#pragma unroll
            for (int i = 0; i < 8; i++) a[i] = As[kk][ty * 8 + i];
#pragma unroll
            for (int j = 0; j < 4; j++) b[j] = Bs[kk][tx * 4 + j];
#pragma unroll
            for (int i = 0; i < 8; i++)
#pragma unroll
                for (int j = 0; j < 4; j++) acc[i][j] = fmaf(a[i], b[j], acc[i][j]);
        }
        __syncthreads();
    }

    // bias
    if (bias) {
        float4 bb = *(const float4*)(bias + col0 + tx * 4);
#pragma unroll
        for (int i = 0; i < 8; i++) {
            acc[i][0] += bb.x; acc[i][1] += bb.y; acc[i][2] += bb.z; acc[i][3] += bb.w;
        }
    }

    // store + local stats
    float ls[4] = {0.f, 0.f, 0.f, 0.f};
    float lq[4] = {0.f, 0.f, 0.f, 0.f};
#pragma unroll
    for (int i = 0; i < 8; i++) {
        int gr = row0 + ty * 8 + i;
        if (gr < M) {
            float4 v = make_float4(acc[i][0], acc[i][1], acc[i][2], acc[i][3]);
            *(float4*)(C + (size_t)gr * N + col0 + tx * 4) = v;
#pragma unroll
            for (int j = 0; j < 4; j++) { ls[j] += acc[i][j]; lq[j] = fmaf(acc[i][j], acc[i][j], lq[j]); }
        }
    }
#pragma unroll
    for (int j = 0; j < 4; j++) {
        atomicAdd(&sSum[tx * 4 + j], ls[j]);
        atomicAdd(&sSq [tx * 4 + j], lq[j]);
    }
    __syncthreads();
    if (tid < 64) {
        atomicAdd(&gsum[col0 + tid], sSum[tid]);
        atomicAdd(&gsq [col0 + tid], sSq [tid]);
    }
}

// ---------------- BN params: a = g*rsqrt(var+eps), b = beta - mean*a ----------------
__global__ void bnp_k(const float* __restrict__ sum, const float* __restrict__ sq,
                      const float* __restrict__ g, const float* __restrict__ beta,
                      float invN, int Cc, float* __restrict__ a, float* __restrict__ b)
{
    int c = blockIdx.x * blockDim.x + threadIdx.x;
    if (c < Cc) {
        float m = sum[c] * invN;
        float v = sq[c] * invN - m * m;
        float s = g[c] * rsqrtf(v + BN_EPS);
        a[c] = s;
        b[c] = beta[c] - m * s;
    }
}

// ---------------- edge CSR build ----------------
__global__ void hist_k(const int* __restrict__ eq) {
    for (int i = blockIdx.x * blockDim.x + threadIdx.x; i < NE; i += gridDim.x * blockDim.x)
        atomicAdd(&d_cnt[eq[i]], 1);
}

__global__ void scan_k() {
    __shared__ int sh[1024];
    int carry = 0;
    for (int base = 0; base < NQ; base += 1024) {
        int i = base + threadIdx.x;
        int v = (i < NQ) ? d_cnt[i] : 0;
        sh[threadIdx.x] = v;
        __syncthreads();
        for (int s = 1; s < 1024; s <<= 1) {
            int t = (threadIdx.x >= s) ? sh[threadIdx.x - s] : 0;
            __syncthreads();
            sh[threadIdx.x] += t;
            __syncthreads();
        }
        int incl = sh[threadIdx.x];
        if (i < NQ) {
            int excl = carry + incl - v;
            d_off[i] = excl;
            d_cur[i] = excl;
        }
        carry += sh[1023];
        __syncthreads();
    }
    if (threadIdx.x == 0) d_off[NQ] = carry;
}

__global__ void scatter_k(const float* __restrict__ refb, const float* __restrict__ qb,
                          const int* __restrict__ er, const int* __restrict__ eq) {
    for (int i = blockIdx.x * blockDim.x + threadIdx.x; i < NE; i += gridDim.x * blockDim.x) {
        int r = er[i], q = eq[i];
        float dx = refb[r * 4 + 1] - qb[q * 4 + 1];
        float dy = refb[r * 4 + 2] - qb[q * 4 + 2];
        float dz = refb[r * 4 + 3] - qb[q * 4 + 3];
        float dist = sqrtf(dx * dx + dy * dy + dz * dz);
        float w = 1.f / (dist + 1e-8f);
        int pos = atomicAdd(&d_cur[q], 1);
        d_er[pos] = r;
        d_ew[pos] = w;
    }
}

// ---------------- per-query gather + BN affine + skip + relu -> x0 ----------------
__global__ void gather_k() {
    int gwarp = (blockIdx.x * blockDim.x + threadIdx.x) >> 5;
    int lane  = threadIdx.x & 31;
    if (gwarp >= NQ) return;
    int beg = d_off[gwarp], end = d_off[gwarp + 1];

    float ws = 0.f;
    for (int p = beg + lane; p < end; p += 32) ws += d_ew[p];
#pragma unroll
    for (int s = 16; s; s >>= 1) ws += __shfl_xor_sync(0xFFFFFFFFu, ws, s);
    float inv = (end > beg) ? 1.f / ws : 0.f;

    const float4* F4 = (const float4*)d_tmpF;
    float4 acc = make_float4(0.f, 0.f, 0.f, 0.f);

    int p = beg;
    for (; p + 4 <= end; p += 4) {
        int r0 = d_er[p], r1 = d_er[p + 1], r2 = d_er[p + 2], r3 = d_er[p + 3];
        float w0 = d_ew[p] * inv, w1 = d_ew[p + 1] * inv, w2 = d_ew[p + 2] * inv, w3 = d_ew[p + 3] * inv;
        float4 f0 = F4[(size_t)r0 * 32 + lane];
        float4 f1 = F4[(size_t)r1 * 32 + lane];
        float4 f2 = F4[(size_t)r2 * 32 + lane];
        float4 f3 = F4[(size_t)r3 * 32 + lane];
        acc.x += w0 * f0.x + w1 * f1.x + w2 * f2.x + w3 * f3.x;
        acc.y += w0 * f0.y + w1 * f1.y + w2 * f2.y + w3 * f3.y;
        acc.z += w0 * f0.z + w1 * f1.z + w2 * f2.z + w3 * f3.z;
        acc.w += w0 * f0.w + w1 * f1.w + w2 * f2.w + w3 * f3.w;
    }
    for (; p < end; p++) {
        int r = d_er[p];
        float w = d_ew[p] * inv;
        float4 f = F4[(size_t)r * 32 + lane];
        acc.x += w * f.x; acc.y += w * f.y; acc.z += w * f.z; acc.w += w * f.w;
    }

    float4 aF = ((const float4*)d_aF)[lane];
    float4 bF = ((const float4*)d_bF)[lane];
    float4 aS = ((const float4*)d_aS)[lane];
    float4 bS = ((const float4*)d_bS)[lane];
    float4 sk = ((const float4*)d_tmpS)[(size_t)gwarp * 32 + lane];
    float he = (end > beg) ? 1.f : 0.f;  // empty query: no bF term (sum of normalized w = 0)

    float4 x;
    x.x = fmaxf(aF.x * acc.x + bF.x * he + aS.x * sk.x + bS.x, 0.f);
    x.y = fmaxf(aF.y * acc.y + bF.y * he + aS.y * sk.y + bS.y, 0.f);
    x.z = fmaxf(aF.z * acc.z + bF.z * he + aS.z * sk.z + bS.z, 0.f);
    x.w = fmaxf(aF.w * acc.w + bF.w * he + aS.w * sk.w + bS.w, 0.f);
    ((float4*)d_x0)[(size_t)gwarp * 32 + lane] = x;
}

// ---------------- final BN+ReLU on tmp2 -> out ----------------
__global__ void final_k(float* __restrict__ out) {
    const float4* T = (const float4*)d_tmp2;
    const float4* A = (const float4*)d_a2;
    const float4* B = (const float4*)d_b2n;
    int total4 = NQ * C2 / 4;
    for (int i = blockIdx.x * blockDim.x + threadIdx.x; i < total4; i += gridDim.x * blockDim.x) {
        float4 v = T[i];
        int c4 = i & (C2 / 4 - 1);
        float4 a = A[c4], b = B[c4];
        float4 o;
        o.x = fmaxf(fmaf(a.x, v.x, b.x), 0.f);
        o.y = fmaxf(fmaf(a.y, v.y, b.y), 0.f);
        o.z = fmaxf(fmaf(a.z, v.z, b.z), 0.f);
        o.w = fmaxf(fmaf(a.w, v.w, b.w), 0.f);
        ((float4*)out)[i] = o;
    }
}

// ---------------- host launch ----------------
extern "C" void kernel_launch(void* const* d_in, const int* in_sizes, int n_in,
                              void* d_out, int out_size)
{
    const float* ref_bxyz   = (const float*)d_in[0];
    const float* ref_feat   = (const float*)d_in[1];
    const float* query_bxyz = (const float*)d_in[2];
    const float* query_feat = (const float*)d_in[3];
    const int*   e_ref      = (const int*)d_in[4];
    const int*   e_query    = (const int*)d_in[5];
    const float* Wf0  = (const float*)d_in[6];
    const float* gf0  = (const float*)d_in[7];
    const float* bf0  = (const float*)d_in[8];
    const float* Ws0  = (const float*)d_in[9];
    const float* gs0  = (const float*)d_in[10];
    const float* bs0  = (const float*)d_in[11];
    const float* W1   = (const float*)d_in[12];
    const float* b1   = (const float*)d_in[13];
    const float* g1   = (const float*)d_in[14];
    const float* beta1= (const float*)d_in[15];
    const float* W2   = (const float*)d_in[16];
    const float* b2   = (const float*)d_in[17];
    const float* g2   = (const float*)d_in[18];
    const float* beta2= (const float*)d_in[19];
    float* out = (float*)d_out;

    float *tmpF, *tmpS, *x0, *tmp1, *tmp2;
    float *sumF, *sqF, *sumS, *sqS, *sum1, *sq1, *sum2, *sq2;
    float *aF, *bF, *aS, *bS, *a1, *b1n, *a2, *b2n;
    cudaGetSymbolAddress((void**)&tmpF, d_tmpF);
    cudaGetSymbolAddress((void**)&tmpS, d_tmpS);
    cudaGetSymbolAddress((void**)&x0,   d_x0);
    cudaGetSymbolAddress((void**)&tmp1, d_tmp1);
    cudaGetSymbolAddress((void**)&tmp2, d_tmp2);
    cudaGetSymbolAddress((void**)&sumF, d_sumF);
    cudaGetSymbolAddress((void**)&sqF,  d_sqF);
    cudaGetSymbolAddress((void**)&sumS, d_sumS);
    cudaGetSymbolAddress((void**)&sqS,  d_sqS);
    cudaGetSymbolAddress((void**)&sum1, d_sum1);
    cudaGetSymbolAddress((void**)&sq1,  d_sq1);
    cudaGetSymbolAddress((void**)&sum2, d_sum2);
    cudaGetSymbolAddress((void**)&sq2,  d_sq2);
    cudaGetSymbolAddress((void**)&aF,   d_aF);
    cudaGetSymbolAddress((void**)&bF,   d_bF);
    cudaGetSymbolAddress((void**)&aS,   d_aS);
    cudaGetSymbolAddress((void**)&bS,   d_bS);
    cudaGetSymbolAddress((void**)&a1,   d_a1);
    cudaGetSymbolAddress((void**)&b1n,  d_b1n);
    cudaGetSymbolAddress((void**)&a2,   d_a2);
    cudaGetSymbolAddress((void**)&b2n,  d_b2n);

    // 0) zero counters + stats
    zero_k<<<128, 256>>>();

    // 1) GEMM F: ref_feat @ Wf0 -> tmpF, stats over NREF
    sgemm_stats<<<dim3(C0 / 64, (NREF + 127) / 128), 256>>>(
        ref_feat, Wf0, nullptr, nullptr, nullptr, tmpF, sumF, sqF, NREF, C0, C0);

    // 2) GEMM S: query_feat @ Ws0 -> tmpS, stats over NQ
    sgemm_stats<<<dim3(C0 / 64, (NQ + 127) / 128), 256>>>(
        query_feat, Ws0, nullptr, nullptr, nullptr, tmpS, sumS, sqS, NQ, C0, C0);

    // 3) BN params for F and S
    bnp_k<<<1, 128>>>(sumF, sqF, gf0, bf0, 1.f / NREF, C0, aF, bF);
    bnp_k<<<1, 128>>>(sumS, sqS, gs0, bs0, 1.f / NQ,   C0, aS, bS);

    // 4) CSR build + edge weights
    hist_k<<<512, 256>>>(e_query);
    scan_k<<<1, 1024>>>();
    scatter_k<<<512, 256>>>(ref_bxyz, query_bxyz, e_ref, e_query);

    // 5) per-query gather -> x0
    gather_k<<<(NQ * 32 + 255) / 256, 256>>>();

    // 6) GEMM 1: x0 @ W1 + b1 -> tmp1, stats
    sgemm_stats<<<dim3(C1 / 64, (NQ + 127) / 128), 256>>>(
        x0, W1, b1, nullptr, nullptr, tmp1, sum1, sq1, NQ, C0, C1);
    bnp_k<<<1, 256>>>(sum1, sq1, g1, beta1, 1.f / NQ, C1, a1, b1n);

    // 7) GEMM 2: bnrelu(tmp1) @ W2 + b2 -> tmp2, stats (BN+ReLU fused into A load)
    sgemm_stats<<<dim3(C2 / 64, (NQ + 127) / 128), 256>>>(
        tmp1, W2, b2, a1, b1n, tmp2, sum2, sq2, NQ, C1, C2);
    bnp_k<<<1, 256>>>(sum2, sq2, g2, beta2, 1.f / NQ, C2, a2, b2n);

    // 8) final BN+ReLU -> out
    final_k<<<512, 256>>>(out);
}

// round 6
// speedup vs baseline: 1.3354x; 1.3354x over previous
#include <cuda_runtime.h>
#include <cuda_bf16.h>
#include <math.h>
#include <stdint.h>

#define NREF 50000
#define NQ   25000
#define NE   400000
#define C0   128
#define C1   256
#define C2   256
#define BN_EPS 1e-5f

// ---------------- scratch (static device globals; no allocations) ----------------
__device__ float d_tmpF[NREF * C0];   // ref_feat @ Wf0 (pre-BN)
__device__ float d_tmpS[NQ * C0];     // query_feat @ Ws0 (pre-BN)
__device__ float d_x0[NQ * C0];       // relu(query_f + query_skip)
__device__ float d_tmp1[NQ * C1];     // x0 @ W1 + b1 (pre-BN)
__device__ float d_tmp2[NQ * C2];     // bnrelu(tmp1) @ W2 + b2 (pre-BN)

__device__ float d_sumF[C0], d_sqF[C0], d_sumS[C0], d_sqS[C0];
__device__ float d_sum1[C1], d_sq1[C1], d_sum2[C2], d_sq2[C2];
__device__ float d_aF[C0], d_bF[C0], d_aS[C0], d_bS[C0];
__device__ float d_a1[C1], d_b1n[C1], d_a2[C2], d_b2n[C2];

__device__ int   d_cnt[NQ];
__device__ int   d_off[NQ + 1];
__device__ int   d_cur[NQ];
__device__ int   d_er[NE];
__device__ float d_ew[NE];

// ---------------- warp MMA helpers (base-arch PTX, works on compute_103) ----------------
__device__ __forceinline__ void ldm4(uint32_t a[4], uint32_t addr) {
    asm volatile("ldmatrix.sync.aligned.m8n8.x4.shared.b16 {%0,%1,%2,%3}, [%4];"
        : "=r"(a[0]), "=r"(a[1]), "=r"(a[2]), "=r"(a[3]) : "r"(addr));
}
__device__ __forceinline__ void ldm4t(uint32_t a[4], uint32_t addr) {
    asm volatile("ldmatrix.sync.aligned.m8n8.x4.trans.shared.b16 {%0,%1,%2,%3}, [%4];"
        : "=r"(a[0]), "=r"(a[1]), "=r"(a[2]), "=r"(a[3]) : "r"(addr));
}
__device__ __forceinline__ void mma16816(float* d, const uint32_t a[4], uint32_t b0, uint32_t b1) {
    asm volatile("mma.sync.aligned.m16n8k16.row.col.f32.bf16.bf16.f32 "
        "{%0,%1,%2,%3}, {%4,%5,%6,%7}, {%8,%9}, {%0,%1,%2,%3};"
        : "+f"(d[0]), "+f"(d[1]), "+f"(d[2]), "+f"(d[3])
        : "r"(a[0]), "r"(a[1]), "r"(a[2]), "r"(a[3]), "r"(b0), "r"(b1));
}
__device__ __forceinline__ uint32_t pack_bf2(float x, float y) {
    __nv_bfloat162 t = __floats2bfloat162_rn(x, y);
    return *(uint32_t*)&t;
}
__device__ __forceinline__ void bsplit4(float4 v, uint32_t& h01, uint32_t& h23,
                                        uint32_t& l01, uint32_t& l23) {
    float hx = __bfloat162float(__float2bfloat16(v.x));
    float hy = __bfloat162float(__float2bfloat16(v.y));
    float hz = __bfloat162float(__float2bfloat16(v.z));
    float hw = __bfloat162float(__float2bfloat16(v.w));
    h01 = pack_bf2(hx, hy); h23 = pack_bf2(hz, hw);
    l01 = pack_bf2(v.x - hx, v.y - hy); l23 = pack_bf2(v.z - hz, v.w - hw);
}

// ---------------- zero init ----------------
__global__ void zero_k() {
    int i = blockIdx.x * blockDim.x + threadIdx.x;
    for (int t = i; t < NQ; t += gridDim.x * blockDim.x) d_cnt[t] = 0;
    if (i < C0) { d_sumF[i] = 0.f; d_sqF[i] = 0.f; d_sumS[i] = 0.f; d_sqS[i] = 0.f; }
    if (i < C1) { d_sum1[i] = 0.f; d_sq1[i] = 0.f; }
    if (i < C2) { d_sum2[i] = 0.f; d_sq2[i] = 0.f; }
}

// ---------------- tensor-core GEMM (mma.sync bf16 hi/lo) with BN-stats epilogue -------
// C[M,N] = f(A)[M,K] @ B[K,N] (+bias);  f(v,k) = relu(v*aT[k]+bT[k]) if aT else v.
// CTA: 128 rows x 128 cols (grid.y = N/128). 256 threads = 8 warps (4 row x 2 col).
// Warp tile 32x64: 2 m16 tiles x 8 n8 tiles. K chunked by 32.
// Accuracy: D += Ahi*Bhi + Ahi*Blo + Alo*Bhi  (bf16 split, lo*lo dropped).
#define SA 40   // A smem stride (bf16): conflict-free for ldmatrix
#define SB 136  // B smem stride (bf16)
__global__ void __launch_bounds__(256) mmagemm(
    const float* __restrict__ A, const float* __restrict__ B,
    const float* __restrict__ bias,
    const float* __restrict__ aT, const float* __restrict__ bT,
    float* __restrict__ C,
    float* __restrict__ gsum, float* __restrict__ gsq,
    int M, int K, int N)
{
    __shared__ __nv_bfloat16 AsH[128 * SA], AsL[128 * SA];
    __shared__ __nv_bfloat16 BsH[32 * SB],  BsL[32 * SB];
    __shared__ float sSum[128], sSq[128];

    const int tid  = threadIdx.x;
    const int lane = tid & 31;
    const int warp = tid >> 5;
    const int wr = warp >> 1;       // warp row 0..3
    const int wc = warp & 1;        // warp col 0..1
    const int row0 = blockIdx.x * 128;
    const int col0 = blockIdx.y * 128;

    if (tid < 128) { sSum[tid] = 0.f; sSq[tid] = 0.f; }

    float acc[2][8][4];
#pragma unroll
    for (int i = 0; i < 2; i++)
#pragma unroll
        for (int j = 0; j < 8; j++)
#pragma unroll
            for (int t = 0; t < 4; t++) acc[i][j][t] = 0.f;

    // conversion indices
    const int ar = tid >> 1;            // A row 0..127
    const int ac = (tid & 1) * 16;      // A col base within chunk
    const int br = tid >> 3;            // B row 0..31
    const int bc = (tid & 7) * 16;      // B col base (local 0..127)
    const int gr_a = row0 + ar;

    uint32_t ash_base = (uint32_t)__cvta_generic_to_shared(AsH);
    uint32_t asl_base = (uint32_t)__cvta_generic_to_shared(AsL);
    uint32_t bsh_base = (uint32_t)__cvta_generic_to_shared(BsH);
    uint32_t bsl_base = (uint32_t)__cvta_generic_to_shared(BsL);

    for (int k0 = 0; k0 < K; k0 += 32) {
        __syncthreads();   // protect smem reuse (also orders sSum zeroing once)

        // ---- convert A chunk: 128 x 32 fp32 -> bf16 hi/lo ----
#pragma unroll
        for (int h = 0; h < 4; h++) {
            int c = ac + h * 4;
            float4 v = make_float4(0.f, 0.f, 0.f, 0.f);
            if (gr_a < M) v = *(const float4*)(A + (size_t)gr_a * K + k0 + c);
            if (aT) {
                int kb = k0 + c;
                v.x = fmaxf(fmaf(v.x, aT[kb + 0], bT[kb + 0]), 0.f);
                v.y = fmaxf(fmaf(v.y, aT[kb + 1], bT[kb + 1]), 0.f);
                v.z = fmaxf(fmaf(v.z, aT[kb + 2], bT[kb + 2]), 0.f);
                v.w = fmaxf(fmaf(v.w, aT[kb + 3], bT[kb + 3]), 0.f);
            }
            uint32_t h01, h23, l01, l23;
            bsplit4(v, h01, h23, l01, l23);
            int base = ar * SA + c;
            *(uint32_t*)&AsH[base]     = h01;
            *(uint32_t*)&AsH[base + 2] = h23;
            *(uint32_t*)&AsL[base]     = l01;
            *(uint32_t*)&AsL[base + 2] = l23;
        }

        // ---- convert B chunk: 32 x 128 fp32 -> bf16 hi/lo ----
#pragma unroll
        for (int h = 0; h < 4; h++) {
            int c = bc + h * 4;
            float4 v = *(const float4*)(B + (size_t)(k0 + br) * N + col0 + c);
            uint32_t h01, h23, l01, l23;
            bsplit4(v, h01, h23, l01, l23);
            int base = br * SB + c;
            *(uint32_t*)&BsH[base]     = h01;
            *(uint32_t*)&BsH[base + 2] = h23;
            *(uint32_t*)&BsL[base]     = l01;
            *(uint32_t*)&BsL[base + 2] = l23;
        }
        __syncthreads();

        // ---- MMA over the chunk: 2 k16 steps ----
#pragma unroll
        for (int kk = 0; kk < 32; kk += 16) {
            uint32_t ah[2][4], al[2][4];
            int arow = lane & 15;
            int acol = kk + ((lane >> 4) << 3);
#pragma unroll
            for (int i = 0; i < 2; i++) {
                int r = wr * 32 + i * 16 + arow;
                uint32_t off = (uint32_t)(r * SA + acol) * 2;
                ldm4(ah[i], ash_base + off);
                ldm4(al[i], asl_base + off);
            }
            int brow = kk + (lane & 15);
            int bcol = wc * 64 + ((lane >> 4) << 3);
#pragma unroll
            for (int g = 0; g < 4; g++) {
                uint32_t bh[4], bl[4];
                uint32_t off = (uint32_t)(brow * SB + bcol + g * 16) * 2;
                ldm4t(bh, bsh_base + off);
                ldm4t(bl, bsl_base + off);
#pragma unroll
                for (int i = 0; i < 2; i++) {
                    mma16816(acc[i][2 * g],     ah[i], bh[0], bh[1]);
                    mma16816(acc[i][2 * g],     ah[i], bl[0], bl[1]);
                    mma16816(acc[i][2 * g],     al[i], bh[0], bh[1]);
                    mma16816(acc[i][2 * g + 1], ah[i], bh[2], bh[3]);
                    mma16816(acc[i][2 * g + 1], ah[i], bl[2], bl[3]);
                    mma16816(acc[i][2 * g + 1], al[i], bh[2], bh[3]);
                }
            }
        }
    }

    // ---------------- epilogue: bias, store, BN stats ----------------
    const int qrow = lane >> 2;
    const int cpo  = (lane & 3) * 2;
#pragma unroll
    for (int j = 0; j < 8; j++) {
        int cl = wc * 64 + j * 8 + cpo;   // local col (0..127)
        int gc = col0 + cl;
        float bx = 0.f, by = 0.f;
        if (bias) { bx = bias[gc]; by = bias[gc + 1]; }
        float se = 0.f, so = 0.f, qe = 0.f, qo = 0.f;
#pragma unroll
        for (int i = 0; i < 2; i++) {
            int r0r = row0 + wr * 32 + i * 16 + qrow;
            int r1r = r0r + 8;
            float d0 = acc[i][j][0] + bx, d1 = acc[i][j][1] + by;
            float d2 = acc[i][j][2] + bx, d3 = acc[i][j][3] + by;
            if (r0r < M) {
                *(float2*)(C + (size_t)r0r * N + gc) = make_float2(d0, d1);
                se += d0; so += d1; qe += d0 * d0; qo += d1 * d1;
            }
            if (r1r < M) {
                *(float2*)(C + (size_t)r1r * N + gc) = make_float2(d2, d3);
                se += d2; so += d3; qe += d2 * d2; qo += d3 * d3;
            }
        }
#pragma unroll
        for (int m = 4; m <= 16; m <<= 1) {
            se += __shfl_xor_sync(0xFFFFFFFFu, se, m);
            so += __shfl_xor_sync(0xFFFFFFFFu, so, m);
            qe += __shfl_xor_sync(0xFFFFFFFFu, qe, m);
            qo += __shfl_xor_sync(0xFFFFFFFFu, qo, m);
        }
        if (lane < 4) {
            atomicAdd(&sSum[cl], se);
            atomicAdd(&sSum[cl + 1], so);
            atomicAdd(&sSq[cl], qe);
            atomicAdd(&sSq[cl + 1], qo);
        }
    }
    __syncthreads();
    if (tid < 128) {
        atomicAdd(&gsum[col0 + tid], sSum[tid]);
        atomicAdd(&gsq[col0 + tid],  sSq[tid]);
    }
}

// ---------------- BN params: a = g*rsqrt(var+eps), b = beta - mean*a ----------------
__global__ void bnp_k(const float* __restrict__ sum, const float* __restrict__ sq,
                      const float* __restrict__ g, const float* __restrict__ beta,
                      float invN, int Cc, float* __restrict__ a, float* __restrict__ b)
{
    int c = blockIdx.x * blockDim.x + threadIdx.x;
    if (c < Cc) {
        float m = sum[c] * invN;
        float v = sq[c] * invN - m * m;
        float s = g[c] * rsqrtf(v + BN_EPS);
        a[c] = s;
        b[c] = beta[c] - m * s;
    }
}

// ---------------- edge CSR build ----------------
__global__ void hist_k(const int* __restrict__ eq) {
    for (int i = blockIdx.x * blockDim.x + threadIdx.x; i < NE; i += gridDim.x * blockDim.x)
        atomicAdd(&d_cnt[eq[i]], 1);
}

__global__ void scan_k() {
    __shared__ int sh[1024];
    int carry = 0;
    for (int base = 0; base < NQ; base += 1024) {
        int i = base + threadIdx.x;
        int v = (i < NQ) ? d_cnt[i] : 0;
        sh[threadIdx.x] = v;
        __syncthreads();
        for (int s = 1; s < 1024; s <<= 1) {
            int t = (threadIdx.x >= s) ? sh[threadIdx.x - s] : 0;
            __syncthreads();
            sh[threadIdx.x] += t;
            __syncthreads();
        }
        int incl = sh[threadIdx.x];
        if (i < NQ) {
            int excl = carry + incl - v;
            d_off[i] = excl;
            d_cur[i] = excl;
        }
        carry += sh[1023];
        __syncthreads();
    }
    if (threadIdx.x == 0) d_off[NQ] = carry;
}

__global__ void scatter_k(const float* __restrict__ refb, const float* __restrict__ qb,
                          const int* __restrict__ er, const int* __restrict__ eq) {
    for (int i = blockIdx.x * blockDim.x + threadIdx.x; i < NE; i += gridDim.x * blockDim.x) {
        int r = er[i], q = eq[i];
        float dx = refb[r * 4 + 1] - qb[q * 4 + 1];
        float dy = refb[r * 4 + 2] - qb[q * 4 + 2];
        float dz = refb[r * 4 + 3] - qb[q * 4 + 3];
        float dist = sqrtf(dx * dx + dy * dy + dz * dz);
        float w = 1.f / (dist + 1e-8f);
        int pos = atomicAdd(&d_cur[q], 1);
        d_er[pos] = r;
        d_ew[pos] = w;
    }
}

// ---------------- per-query gather + BN affine + skip + relu -> x0 ----------------
__global__ void gather_k() {
    int gwarp = (blockIdx.x * blockDim.x + threadIdx.x) >> 5;
    int lane  = threadIdx.x & 31;
    if (gwarp >= NQ) return;
    int beg = d_off[gwarp], end = d_off[gwarp + 1];

    float ws = 0.f;
    for (int p = beg + lane; p < end; p += 32) ws += d_ew[p];
#pragma unroll
    for (int s = 16; s; s >>= 1) ws += __shfl_xor_sync(0xFFFFFFFFu, ws, s);
    float inv = (end > beg) ? 1.f / ws : 0.f;

    const float4* F4 = (const float4*)d_tmpF;
    float4 acc = make_float4(0.f, 0.f, 0.f, 0.f);

    int p = beg;
    for (; p + 4 <= end; p += 4) {
        int r0 = d_er[p], r1 = d_er[p + 1], r2 = d_er[p + 2], r3 = d_er[p + 3];
        float w0 = d_ew[p] * inv, w1 = d_ew[p + 1] * inv, w2 = d_ew[p + 2] * inv, w3 = d_ew[p + 3] * inv;
        float4 f0 = F4[(size_t)r0 * 32 + lane];
        float4 f1 = F4[(size_t)r1 * 32 + lane];
        float4 f2 = F4[(size_t)r2 * 32 + lane];
        float4 f3 = F4[(size_t)r3 * 32 + lane];
        acc.x += w0 * f0.x + w1 * f1.x + w2 * f2.x + w3 * f3.x;
        acc.y += w0 * f0.y + w1 * f1.y + w2 * f2.y + w3 * f3.y;
        acc.z += w0 * f0.z + w1 * f1.z + w2 * f2.z + w3 * f3.z;
        acc.w += w0 * f0.w + w1 * f1.w + w2 * f2.w + w3 * f3.w;
    }
    for (; p < end; p++) {
        int r = d_er[p];
        float w = d_ew[p] * inv;
        float4 f = F4[(size_t)r * 32 + lane];
        acc.x += w * f.x; acc.y += w * f.y; acc.z += w * f.z; acc.w += w * f.w;
    }

    float4 aF = ((const float4*)d_aF)[lane];
    float4 bF = ((const float4*)d_bF)[lane];
    float4 aS = ((const float4*)d_aS)[lane];
    float4 bS = ((const float4*)d_bS)[lane];
    float4 sk = ((const float4*)d_tmpS)[(size_t)gwarp * 32 + lane];
    float he = (end > beg) ? 1.f : 0.f;

    float4 x;
    x.x = fmaxf(aF.x * acc.x + bF.x * he + aS.x * sk.x + bS.x, 0.f);
    x.y = fmaxf(aF.y * acc.y + bF.y * he + aS.y * sk.y + bS.y, 0.f);
    x.z = fmaxf(aF.z * acc.z + bF.z * he + aS.z * sk.z + bS.z, 0.f);
    x.w = fmaxf(aF.w * acc.w + bF.w * he + aS.w * sk.w + bS.w, 0.f);
    ((float4*)d_x0)[(size_t)gwarp * 32 + lane] = x;
}

// ---------------- final BN+ReLU on tmp2 -> out ----------------
__global__ void final_k(float* __restrict__ out) {
    const float4* T = (const float4*)d_tmp2;
    const float4* A = (const float4*)d_a2;
    const float4* B = (const float4*)d_b2n;
    int total4 = NQ * C2 / 4;
    for (int i = blockIdx.x * blockDim.x + threadIdx.x; i < total4; i += gridDim.x * blockDim.x) {
        float4 v = T[i];
        int c4 = i & (C2 / 4 - 1);
        float4 a = A[c4], b = B[c4];
        float4 o;
        o.x = fmaxf(fmaf(a.x, v.x, b.x), 0.f);
        o.y = fmaxf(fmaf(a.y, v.y, b.y), 0.f);
        o.z = fmaxf(fmaf(a.z, v.z, b.z), 0.f);
        o.w = fmaxf(fmaf(a.w, v.w, b.w), 0.f);
        ((float4*)out)[i] = o;
    }
}

// ---------------- host launch ----------------
extern "C" void kernel_launch(void* const* d_in, const int* in_sizes, int n_in,
                              void* d_out, int out_size)
{
    const float* ref_bxyz   = (const float*)d_in[0];
    const float* ref_feat   = (const float*)d_in[1];
    const float* query_bxyz = (const float*)d_in[2];
    const float* query_feat = (const float*)d_in[3];
    const int*   e_ref      = (const int*)d_in[4];
    const int*   e_query    = (const int*)d_in[5];
    const float* Wf0  = (const float*)d_in[6];
    const float* gf0  = (const float*)d_in[7];
    const float* bf0  = (const float*)d_in[8];
    const float* Ws0  = (const float*)d_in[9];
    const float* gs0  = (const float*)d_in[10];
    const float* bs0  = (const float*)d_in[11];
    const float* W1   = (const float*)d_in[12];
    const float* b1   = (const float*)d_in[13];
    const float* g1   = (const float*)d_in[14];
    const float* beta1= (const float*)d_in[15];
    const float* W2   = (const float*)d_in[16];
    const float* b2   = (const float*)d_in[17];
    const float* g2   = (const float*)d_in[18];
    const float* beta2= (const float*)d_in[19];
    float* out = (float*)d_out;

    float *tmpF, *tmpS, *x0, *tmp1, *tmp2;
    float *sumF, *sqF, *sumS, *sqS, *sum1, *sq1, *sum2, *sq2;
    float *aF, *bF, *aS, *bS, *a1, *b1n, *a2, *b2n;
    cudaGetSymbolAddress((void**)&tmpF, d_tmpF);
    cudaGetSymbolAddress((void**)&tmpS, d_tmpS);
    cudaGetSymbolAddress((void**)&x0,   d_x0);
    cudaGetSymbolAddress((void**)&tmp1, d_tmp1);
    cudaGetSymbolAddress((void**)&tmp2, d_tmp2);
    cudaGetSymbolAddress((void**)&sumF, d_sumF);
    cudaGetSymbolAddress((void**)&sqF,  d_sqF);
    cudaGetSymbolAddress((void**)&sumS, d_sumS);
    cudaGetSymbolAddress((void**)&sqS,  d_sqS);
    cudaGetSymbolAddress((void**)&sum1, d_sum1);
    cudaGetSymbolAddress((void**)&sq1,  d_sq1);
    cudaGetSymbolAddress((void**)&sum2, d_sum2);
    cudaGetSymbolAddress((void**)&sq2,  d_sq2);
    cudaGetSymbolAddress((void**)&aF,   d_aF);
    cudaGetSymbolAddress((void**)&bF,   d_bF);
    cudaGetSymbolAddress((void**)&aS,   d_aS);
    cudaGetSymbolAddress((void**)&bS,   d_bS);
    cudaGetSymbolAddress((void**)&a1,   d_a1);
    cudaGetSymbolAddress((void**)&b1n,  d_b1n);
    cudaGetSymbolAddress((void**)&a2,   d_a2);
    cudaGetSymbolAddress((void**)&b2n,  d_b2n);

    // 0) zero counters + stats
    zero_k<<<128, 256>>>();

    // 1) GEMM F: ref_feat @ Wf0 -> tmpF  (M=50000, K=128, N=128)
    mmagemm<<<dim3((NREF + 127) / 128, 1), 256>>>(
        ref_feat, Wf0, nullptr, nullptr, nullptr, tmpF, sumF, sqF, NREF, C0, C0);

    // 2) GEMM S: query_feat @ Ws0 -> tmpS
    mmagemm<<<dim3((NQ + 127) / 128, 1), 256>>>(
        query_feat, Ws0, nullptr, nullptr, nullptr, tmpS, sumS, sqS, NQ, C0, C0);

    // 3) BN params for F and S
    bnp_k<<<1, 128>>>(sumF, sqF, gf0, bf0, 1.f / NREF, C0, aF, bF);
    bnp_k<<<1, 128>>>(sumS, sqS, gs0, bs0, 1.f / NQ,   C0, aS, bS);

    // 4) CSR build + edge weights
    hist_k<<<512, 256>>>(e_query);
    scan_k<<<1, 1024>>>();
    scatter_k<<<512, 256>>>(ref_bxyz, query_bxyz, e_ref, e_query);

    // 5) per-query gather -> x0
    gather_k<<<(NQ * 32 + 255) / 256, 256>>>();

    // 6) GEMM 1: x0 @ W1 + b1 -> tmp1 (M=25000, K=128, N=256)
    mmagemm<<<dim3((NQ + 127) / 128, 2), 256>>>(
        x0, W1, b1, nullptr, nullptr, tmp1, sum1, sq1, NQ, C0, C1);
    bnp_k<<<1, 256>>>(sum1, sq1, g1, beta1, 1.f / NQ, C1, a1, b1n);

    // 7) GEMM 2: bnrelu(tmp1) @ W2 + b2 -> tmp2 (K=256, N=256, BN+ReLU fused into A load)
    mmagemm<<<dim3((NQ + 127) / 128, 2), 256>>>(
        tmp1, W2, b2, a1, b1n, tmp2, sum2, sq2, NQ, C2, C2);
    bnp_k<<<1, 256>>>(sum2, sq2, g2, beta2, 1.f / NQ, C2, a2, b2n);

    // 8) final BN+ReLU -> out
    final_k<<<512, 256>>>(out);
}

// round 7
// speedup vs baseline: 1.3726x; 1.0278x over previous
#include <cuda_runtime.h>
#include <cuda_bf16.h>
#include <math.h>
#include <stdint.h>

#define NREF 50000
#define NQ   25000
#define NE   400000
#define C0   128
#define C1   256
#define C2   256
#define BN_EPS 1e-5f

// ---------------- scratch (static device globals; no allocations) ----------------
__device__ float d_tmpF[NREF * C0];   // ref_feat @ Wf0 (pre-BN)
__device__ float d_tmpS[NQ * C0];     // query_feat @ Ws0 (pre-BN)
__device__ float d_x0[NQ * C0];       // relu(query_f + query_skip)
__device__ float d_tmp1[NQ * C1];     // x0 @ W1 + b1 (pre-BN)
__device__ float d_tmp2[NQ * C2];     // bnrelu(tmp1) @ W2 + b2 (pre-BN)

__device__ float d_sumF[C0], d_sqF[C0], d_sumS[C0], d_sqS[C0];
__device__ float d_sum1[C1], d_sq1[C1], d_sum2[C2], d_sq2[C2];

__device__ int   d_cnt[NQ];
__device__ int   d_off[NQ + 1];
__device__ int   d_cur[NQ];
__device__ int   d_er[NE];
__device__ float d_ew[NE];

// ---------------- warp MMA helpers (base-arch PTX, works on compute_103) ----------------
__device__ __forceinline__ void ldm4(uint32_t a[4], uint32_t addr) {
    asm volatile("ldmatrix.sync.aligned.m8n8.x4.shared.b16 {%0,%1,%2,%3}, [%4];"
        : "=r"(a[0]), "=r"(a[1]), "=r"(a[2]), "=r"(a[3]) : "r"(addr));
}
__device__ __forceinline__ void ldm4t(uint32_t a[4], uint32_t addr) {
    asm volatile("ldmatrix.sync.aligned.m8n8.x4.trans.shared.b16 {%0,%1,%2,%3}, [%4];"
        : "=r"(a[0]), "=r"(a[1]), "=r"(a[2]), "=r"(a[3]) : "r"(addr));
}
__device__ __forceinline__ void mma16816(float* d, const uint32_t a[4], uint32_t b0, uint32_t b1) {
    asm volatile("mma.sync.aligned.m16n8k16.row.col.f32.bf16.bf16.f32 "
        "{%0,%1,%2,%3}, {%4,%5,%6,%7}, {%8,%9}, {%0,%1,%2,%3};"
        : "+f"(d[0]), "+f"(d[1]), "+f"(d[2]), "+f"(d[3])
        : "r"(a[0]), "r"(a[1]), "r"(a[2]), "r"(a[3]), "r"(b0), "r"(b1));
}
__device__ __forceinline__ uint32_t pack_bf2(float x, float y) {
    __nv_bfloat162 t = __floats2bfloat162_rn(x, y);
    return *(uint32_t*)&t;
}
__device__ __forceinline__ void bsplit4(float4 v, uint32_t& h01, uint32_t& h23,
                                        uint32_t& l01, uint32_t& l23) {
    float hx = __bfloat162float(__float2bfloat16(v.x));
    float hy = __bfloat162float(__float2bfloat16(v.y));
    float hz = __bfloat162float(__float2bfloat16(v.z));
    float hw = __bfloat162float(__float2bfloat16(v.w));
    h01 = pack_bf2(hx, hy); h23 = pack_bf2(hz, hw);
    l01 = pack_bf2(v.x - hx, v.y - hy); l23 = pack_bf2(v.z - hz, v.w - hw);
}

// ---------------- zero init ----------------
__global__ void zero_k() {
    int i = blockIdx.x * blockDim.x + threadIdx.x;
    for (int t = i; t < NQ; t += gridDim.x * blockDim.x) d_cnt[t] = 0;
    if (i < C0) { d_sumF[i] = 0.f; d_sqF[i] = 0.f; d_sumS[i] = 0.f; d_sqS[i] = 0.f; }
    if (i < C1) { d_sum1[i] = 0.f; d_sq1[i] = 0.f; }
    if (i < C2) { d_sum2[i] = 0.f; d_sq2[i] = 0.f; }
}

// ---------------- tensor-core GEMM (mma.sync bf16 hi/lo) with BN-stats epilogue -------
// C[M,N] = f(A)[M,K] @ B[K,N] (+bias).
// If bnG != null: f(v,k) = relu(v*a[k]+b[k]) where (a,b) are computed in-block from
// (bnSum, bnSq, bnG, bnBeta, bnInv). Else f = identity.
// CTA: 128 rows x 128 cols (grid.y = N/128). 256 threads = 8 warps (4 row x 2 col).
// Warp tile 32x64. K chunked by 32, next A-chunk register-prefetched during MMA.
// Accuracy: D += Ahi*Bhi + Ahi*Blo + Alo*Bhi  (bf16 split, lo*lo dropped).
#define SA 40   // A smem stride (bf16): conflict-free for ldmatrix
#define SB 136  // B smem stride (bf16)
__global__ void __launch_bounds__(256) mmagemm(
    const float* __restrict__ A, const float* __restrict__ B,
    const float* __restrict__ bias,
    const float* __restrict__ bnSum, const float* __restrict__ bnSq,
    const float* __restrict__ bnG, const float* __restrict__ bnBeta, float bnInv,
    float* __restrict__ C,
    float* __restrict__ gsum, float* __restrict__ gsq,
    int M, int K, int N)
{
    __shared__ __nv_bfloat16 AsH[128 * SA], AsL[128 * SA];
    __shared__ __nv_bfloat16 BsH[32 * SB],  BsL[32 * SB];
    __shared__ float sSum[128], sSq[128];
    __shared__ float aSm[256], bSm[256];

    const int tid  = threadIdx.x;
    const int lane = tid & 31;
    const int warp = tid >> 5;
    const int wr = warp >> 1;       // warp row 0..3
    const int wc = warp & 1;        // warp col 0..1
    const int row0 = blockIdx.x * 128;
    const int col0 = blockIdx.y * 128;

    if (tid < 128) { sSum[tid] = 0.f; sSq[tid] = 0.f; }
    if (bnG && tid < K) {           // K==256 when BN path is used
        float m = bnSum[tid] * bnInv;
        float vv = bnSq[tid] * bnInv - m * m;
        float s = bnG[tid] * rsqrtf(vv + BN_EPS);
        aSm[tid] = s;
        bSm[tid] = bnBeta[tid] - m * s;
    }

    float acc[2][8][4];
#pragma unroll
    for (int i = 0; i < 2; i++)
#pragma unroll
        for (int j = 0; j < 8; j++)
#pragma unroll
            for (int t = 0; t < 4; t++) acc[i][j][t] = 0.f;

    // conversion indices
    const int ar = tid >> 1;            // A row 0..127
    const int ac = (tid & 1) * 16;      // A col base within chunk
    const int br = tid >> 3;            // B row 0..31
    const int bc = (tid & 7) * 16;      // B col base (local 0..127)
    const int gr_a = row0 + ar;
    const bool aval = gr_a < M;
    const float* Arow = A + (size_t)gr_a * K + ac;

    uint32_t ash_base = (uint32_t)__cvta_generic_to_shared(AsH);
    uint32_t asl_base = (uint32_t)__cvta_generic_to_shared(AsL);
    uint32_t bsh_base = (uint32_t)__cvta_generic_to_shared(BsH);
    uint32_t bsl_base = (uint32_t)__cvta_generic_to_shared(BsL);

    const int nChunks = K / 32;

    // prefetch A chunk 0 into registers
    float4 va[4];
#pragma unroll
    for (int h = 0; h < 4; h++)
        va[h] = aval ? *(const float4*)(Arow + h * 4) : make_float4(0.f, 0.f, 0.f, 0.f);

    for (int chunk = 0; chunk < nChunks; chunk++) {
        const int k0 = chunk * 32;
        __syncthreads();   // smem free (MMA of previous chunk complete); also orders aSm/sSum init

        // ---- convert prefetched A chunk: apply BN affine if requested ----
#pragma unroll
        for (int h = 0; h < 4; h++) {
            int c = ac + h * 4;
            float4 v = va[h];
            if (bnG) {
                int kb = k0 + c;
                v.x = fmaxf(fmaf(v.x, aSm[kb + 0], bSm[kb + 0]), 0.f);
                v.y = fmaxf(fmaf(v.y, aSm[kb + 1], bSm[kb + 1]), 0.f);
                v.z = fmaxf(fmaf(v.z, aSm[kb + 2], bSm[kb + 2]), 0.f);
                v.w = fmaxf(fmaf(v.w, aSm[kb + 3], bSm[kb + 3]), 0.f);
            }
            uint32_t h01, h23, l01, l23;
            bsplit4(v, h01, h23, l01, l23);
            int base = ar * SA + c;
            *(uint32_t*)&AsH[base]     = h01;
            *(uint32_t*)&AsH[base + 2] = h23;
            *(uint32_t*)&AsL[base]     = l01;
            *(uint32_t*)&AsL[base + 2] = l23;
        }

        // ---- convert B chunk (L2-hot weights) ----
#pragma unroll
        for (int h = 0; h < 4; h++) {
            int c = bc + h * 4;
            float4 v = *(const float4*)(B + (size_t)(k0 + br) * N + col0 + c);
            uint32_t h01, h23, l01, l23;
            bsplit4(v, h01, h23, l01, l23);
            int base = br * SB + c;
            *(uint32_t*)&BsH[base]     = h01;
            *(uint32_t*)&BsH[base + 2] = h23;
            *(uint32_t*)&BsL[base]     = l01;
            *(uint32_t*)&BsL[base + 2] = l23;
        }
        __syncthreads();

        // ---- prefetch next A chunk (overlaps with MMA below) ----
        if (chunk + 1 < nChunks) {
            const float* An = Arow + (size_t)(k0 + 32);
#pragma unroll
            for (int h = 0; h < 4; h++)
                va[h] = aval ? *(const float4*)(An + h * 4) : make_float4(0.f, 0.f, 0.f, 0.f);
        }

        // ---- MMA over the chunk: 2 k16 steps ----
#pragma unroll
        for (int kk = 0; kk < 32; kk += 16) {
            uint32_t ah[2][4], al[2][4];
            int arow = lane & 15;
            int acol = kk + ((lane >> 4) << 3);
#pragma unroll
            for (int i = 0; i < 2; i++) {
                int r = wr * 32 + i * 16 + arow;
                uint32_t off = (uint32_t)(r * SA + acol) * 2;
                ldm4(ah[i], ash_base + off);
                ldm4(al[i], asl_base + off);
            }
            int brow = kk + (lane & 15);
            int bcol = wc * 64 + ((lane >> 4) << 3);
#pragma unroll
            for (int g = 0; g < 4; g++) {
                uint32_t bh[4], bl[4];
                uint32_t off = (uint32_t)(brow * SB + bcol + g * 16) * 2;
                ldm4t(bh, bsh_base + off);
                ldm4t(bl, bsl_base + off);
#pragma unroll
                for (int i = 0; i < 2; i++) {
                    mma16816(acc[i][2 * g],     ah[i], bh[0], bh[1]);
                    mma16816(acc[i][2 * g],     ah[i], bl[0], bl[1]);
                    mma16816(acc[i][2 * g],     al[i], bh[0], bh[1]);
                    mma16816(acc[i][2 * g + 1], ah[i], bh[2], bh[3]);
                    mma16816(acc[i][2 * g + 1], ah[i], bl[2], bl[3]);
                    mma16816(acc[i][2 * g + 1], al[i], bh[2], bh[3]);
                }
            }
        }
    }

    // ---------------- epilogue: bias, store, BN stats ----------------
    const int qrow = lane >> 2;
    const int cpo  = (lane & 3) * 2;
#pragma unroll
    for (int j = 0; j < 8; j++) {
        int cl = wc * 64 + j * 8 + cpo;   // local col (0..127)
        int gc = col0 + cl;
        float bx = 0.f, by = 0.f;
        if (bias) { bx = bias[gc]; by = bias[gc + 1]; }
        float se = 0.f, so = 0.f, qe = 0.f, qo = 0.f;
#pragma unroll
        for (int i = 0; i < 2; i++) {
            int r0r = row0 + wr * 32 + i * 16 + qrow;
            int r1r = r0r + 8;
            float d0 = acc[i][j][0] + bx, d1 = acc[i][j][1] + by;
            float d2 = acc[i][j][2] + bx, d3 = acc[i][j][3] + by;
            if (r0r < M) {
                *(float2*)(C + (size_t)r0r * N + gc) = make_float2(d0, d1);
                se += d0; so += d1; qe += d0 * d0; qo += d1 * d1;
            }
            if (r1r < M) {
                *(float2*)(C + (size_t)r1r * N + gc) = make_float2(d2, d3);
                se += d2; so += d3; qe += d2 * d2; qo += d3 * d3;
            }
        }
#pragma unroll
        for (int m = 4; m <= 16; m <<= 1) {
            se += __shfl_xor_sync(0xFFFFFFFFu, se, m);
            so += __shfl_xor_sync(0xFFFFFFFFu, so, m);
            qe += __shfl_xor_sync(0xFFFFFFFFu, qe, m);
            qo += __shfl_xor_sync(0xFFFFFFFFu, qo, m);
        }
        if (lane < 4) {
            atomicAdd(&sSum[cl], se);
            atomicAdd(&sSum[cl + 1], so);
            atomicAdd(&sSq[cl], qe);
            atomicAdd(&sSq[cl + 1], qo);
        }
    }
    __syncthreads();
    if (tid < 128) {
        atomicAdd(&gsum[col0 + tid], sSum[tid]);
        atomicAdd(&gsq[col0 + tid],  sSq[tid]);
    }
}

// ---------------- edge CSR build ----------------
__global__ void hist_k(const int* __restrict__ eq) {
    for (int i = blockIdx.x * blockDim.x + threadIdx.x; i < NE; i += gridDim.x * blockDim.x)
        atomicAdd(&d_cnt[eq[i]], 1);
}

// single-block scan: each thread serially handles PER contiguous counters, then
// one 1024-wide Hillis-Steele combines thread totals (20 syncs total).
#define SCAN_PER ((NQ + 1023) / 1024)
__global__ void __launch_bounds__(1024) scan_k() {
    __shared__ int sh[1024];
    const int t = threadIdx.x;
    const int base = t * SCAN_PER;
    int v[SCAN_PER];
    int s = 0;
#pragma unroll
    for (int j = 0; j < SCAN_PER; j++) {
        int i = base + j;
        int c = (i < NQ) ? d_cnt[i] : 0;
        v[j] = s;
        s += c;
    }
    sh[t] = s;
    __syncthreads();
    for (int d = 1; d < 1024; d <<= 1) {
        int x = (t >= d) ? sh[t - d] : 0;
        __syncthreads();
        sh[t] += x;
        __syncthreads();
    }
    int excl = sh[t] - s;
#pragma unroll
    for (int j = 0; j < SCAN_PER; j++) {
        int i = base + j;
        if (i < NQ) {
            int o = excl + v[j];
            d_off[i] = o;
            d_cur[i] = o;
        }
    }
    if (t == 1023) d_off[NQ] = sh[1023];
}

__global__ void scatter_k(const float* __restrict__ refb, const float* __restrict__ qb,
                          const int* __restrict__ er, const int* __restrict__ eq) {
    for (int i = blockIdx.x * blockDim.x + threadIdx.x; i < NE; i += gridDim.x * blockDim.x) {
        int r = er[i], q = eq[i];
        float dx = refb[r * 4 + 1] - qb[q * 4 + 1];
        float dy = refb[r * 4 + 2] - qb[q * 4 + 2];
        float dz = refb[r * 4 + 3] - qb[q * 4 + 3];
        float dist = sqrtf(dx * dx + dy * dy + dz * dz);
        float w = 1.f / (dist + 1e-8f);
        int pos = atomicAdd(&d_cur[q], 1);
        d_er[pos] = r;
        d_ew[pos] = w;
    }
}

// ---------------- per-query gather + inline BN + skip + relu -> x0 ----------------
__global__ void __launch_bounds__(256) gather_k(
    const float* __restrict__ gf0, const float* __restrict__ bf0,
    const float* __restrict__ gs0, const float* __restrict__ bs0)
{
    __shared__ float aFs[C0], bFs[C0], aSs[C0], bSs[C0];
    const int tid = threadIdx.x;

    // compute BN affine params in-block (redundant per block; trivially cheap)
    if (tid < 128) {
        float m = d_sumF[tid] * (1.f / NREF);
        float vv = d_sqF[tid] * (1.f / NREF) - m * m;
        float s = gf0[tid] * rsqrtf(vv + BN_EPS);
        aFs[tid] = s;
        bFs[tid] = bf0[tid] - m * s;
    } else {
        int c = tid - 128;
        float m = d_sumS[c] * (1.f / NQ);
        float vv = d_sqS[c] * (1.f / NQ) - m * m;
        float s = gs0[c] * rsqrtf(vv + BN_EPS);
        aSs[c] = s;
        bSs[c] = bs0[c] - m * s;
    }
    __syncthreads();

    int gwarp = (blockIdx.x * blockDim.x + tid) >> 5;
    int lane  = tid & 31;
    if (gwarp >= NQ) return;
    int beg = d_off[gwarp], end = d_off[gwarp + 1];

    float ws = 0.f;
    for (int p = beg + lane; p < end; p += 32) ws += d_ew[p];
#pragma unroll
    for (int s = 16; s; s >>= 1) ws += __shfl_xor_sync(0xFFFFFFFFu, ws, s);
    float inv = (end > beg) ? 1.f / ws : 0.f;

    const float4* F4 = (const float4*)d_tmpF;
    float4 acc = make_float4(0.f, 0.f, 0.f, 0.f);

    int p = beg;
    for (; p + 4 <= end; p += 4) {
        int r0 = d_er[p], r1 = d_er[p + 1], r2 = d_er[p + 2], r3 = d_er[p + 3];
        float w0 = d_ew[p] * inv, w1 = d_ew[p + 1] * inv, w2 = d_ew[p + 2] * inv, w3 = d_ew[p + 3] * inv;
        float4 f0 = F4[(size_t)r0 * 32 + lane];
        float4 f1 = F4[(size_t)r1 * 32 + lane];
        float4 f2 = F4[(size_t)r2 * 32 + lane];
        float4 f3 = F4[(size_t)r3 * 32 + lane];
        acc.x += w0 * f0.x + w1 * f1.x + w2 * f2.x + w3 * f3.x;
        acc.y += w0 * f0.y + w1 * f1.y + w2 * f2.y + w3 * f3.y;
        acc.z += w0 * f0.z + w1 * f1.z + w2 * f2.z + w3 * f3.z;
        acc.w += w0 * f0.w + w1 * f1.w + w2 * f2.w + w3 * f3.w;
    }
    for (; p < end; p++) {
        int r = d_er[p];
        float w = d_ew[p] * inv;
        float4 f = F4[(size_t)r * 32 + lane];
        acc.x += w * f.x; acc.y += w * f.y; acc.z += w * f.z; acc.w += w * f.w;
    }

    float4 aF = ((const float4*)aFs)[lane];
    float4 bF = ((const float4*)bFs)[lane];
    float4 aS = ((const float4*)aSs)[lane];
    float4 bS = ((const float4*)bSs)[lane];
    float4 sk = ((const float4*)d_tmpS)[(size_t)gwarp * 32 + lane];
    float he = (end > beg) ? 1.f : 0.f;

    float4 x;
    x.x = fmaxf(aF.x * acc.x + bF.x * he + aS.x * sk.x + bS.x, 0.f);
    x.y = fmaxf(aF.y * acc.y + bF.y * he + aS.y * sk.y + bS.y, 0.f);
    x.z = fmaxf(aF.z * acc.z + bF.z * he + aS.z * sk.z + bS.z, 0.f);
    x.w = fmaxf(aF.w * acc.w + bF.w * he + aS.w * sk.w + bS.w, 0.f);
    ((float4*)d_x0)[(size_t)gwarp * 32 + lane] = x;
}

// ---------------- final BN+ReLU on tmp2 -> out (BN affine computed inline) ------------
__global__ void __launch_bounds__(256) final_k(
    const float* __restrict__ g2, const float* __restrict__ beta2, float* __restrict__ out)
{
    __shared__ float a2s[C2], b2s[C2];
    const int tid = threadIdx.x;
    {
        float m = d_sum2[tid] * (1.f / NQ);
        float vv = d_sq2[tid] * (1.f / NQ) - m * m;
        float s = g2[tid] * rsqrtf(vv + BN_EPS);
        a2s[tid] = s;
        b2s[tid] = beta2[tid] - m * s;
    }
    __syncthreads();

    const float4* T = (const float4*)d_tmp2;
    const float4* A = (const float4*)a2s;
    const float4* B = (const float4*)b2s;
    int total4 = NQ * C2 / 4;
    for (int i = blockIdx.x * blockDim.x + tid; i < total4; i += gridDim.x * blockDim.x) {
        float4 v = T[i];
        int c4 = i & (C2 / 4 - 1);
        float4 a = A[c4], b = B[c4];
        float4 o;
        o.x = fmaxf(fmaf(a.x, v.x, b.x), 0.f);
        o.y = fmaxf(fmaf(a.y, v.y, b.y), 0.f);
        o.z = fmaxf(fmaf(a.z, v.z, b.z), 0.f);
        o.w = fmaxf(fmaf(a.w, v.w, b.w), 0.f);
        ((float4*)out)[i] = o;
    }
}

// ---------------- host launch ----------------
extern "C" void kernel_launch(void* const* d_in, const int* in_sizes, int n_in,
                              void* d_out, int out_size)
{
    const float* ref_bxyz   = (const float*)d_in[0];
    const float* ref_feat   = (const float*)d_in[1];
    const float* query_bxyz = (const float*)d_in[2];
    const float* query_feat = (const float*)d_in[3];
    const int*   e_ref      = (const int*)d_in[4];
    const int*   e_query    = (const int*)d_in[5];
    const float* Wf0  = (const float*)d_in[6];
    const float* gf0  = (const float*)d_in[7];
    const float* bf0  = (const float*)d_in[8];
    const float* Ws0  = (const float*)d_in[9];
    const float* gs0  = (const float*)d_in[10];
    const float* bs0  = (const float*)d_in[11];
    const float* W1   = (const float*)d_in[12];
    const float* b1   = (const float*)d_in[13];
    const float* g1   = (const float*)d_in[14];
    const float* beta1= (const float*)d_in[15];
    const float* W2   = (const float*)d_in[16];
    const float* b2   = (const float*)d_in[17];
    const float* g2   = (const float*)d_in[18];
    const float* beta2= (const float*)d_in[19];
    float* out = (float*)d_out;

    float *tmpF, *tmpS, *x0, *tmp1, *tmp2;
    float *sumF, *sqF, *sumS, *sqS, *sum1, *sq1, *sum2, *sq2;
    cudaGetSymbolAddress((void**)&tmpF, d_tmpF);
    cudaGetSymbolAddress((void**)&tmpS, d_tmpS);
    cudaGetSymbolAddress((void**)&x0,   d_x0);
    cudaGetSymbolAddress((void**)&tmp1, d_tmp1);
    cudaGetSymbolAddress((void**)&tmp2, d_tmp2);
    cudaGetSymbolAddress((void**)&sumF, d_sumF);
    cudaGetSymbolAddress((void**)&sqF,  d_sqF);
    cudaGetSymbolAddress((void**)&sumS, d_sumS);
    cudaGetSymbolAddress((void**)&sqS,  d_sqS);
    cudaGetSymbolAddress((void**)&sum1, d_sum1);
    cudaGetSymbolAddress((void**)&sq1,  d_sq1);
    cudaGetSymbolAddress((void**)&sum2, d_sum2);
    cudaGetSymbolAddress((void**)&sq2,  d_sq2);

    // 0) zero counters + stats
    zero_k<<<128, 256>>>();

    // 1) CSR build + edge weights (independent of GEMMs; first so ncu lands on a GEMM)
    hist_k<<<512, 256>>>(e_query);
    scan_k<<<1, 1024>>>();
    scatter_k<<<512, 256>>>(ref_bxyz, query_bxyz, e_ref, e_query);

    // 2) GEMM F: ref_feat @ Wf0 -> tmpF  (M=50000, K=128, N=128)
    mmagemm<<<dim3((NREF + 127) / 128, 1), 256>>>(
        ref_feat, Wf0, nullptr,
        nullptr, nullptr, nullptr, nullptr, 0.f,
        tmpF, sumF, sqF, NREF, C0, C0);

    // 3) GEMM S: query_feat @ Ws0 -> tmpS
    mmagemm<<<dim3((NQ + 127) / 128, 1), 256>>>(
        query_feat, Ws0, nullptr,
        nullptr, nullptr, nullptr, nullptr, 0.f,
        tmpS, sumS, sqS, NQ, C0, C0);

    // 4) per-query gather (BN affine for F and S computed inline) -> x0
    gather_k<<<(NQ * 32 + 255) / 256, 256>>>(gf0, bf0, gs0, bs0);

    // 5) GEMM 1: x0 @ W1 + b1 -> tmp1 (M=25000, K=128, N=256)
    mmagemm<<<dim3((NQ + 127) / 128, 2), 256>>>(
        x0, W1, b1,
        nullptr, nullptr, nullptr, nullptr, 0.f,
        tmp1, sum1, sq1, NQ, C0, C1);

    // 6) GEMM 2: bnrelu(tmp1) @ W2 + b2 -> tmp2 (K=256, N=256; BN params computed in-block)
    mmagemm<<<dim3((NQ + 127) / 128, 2), 256>>>(
        tmp1, W2, b2,
        sum1, sq1, g1, beta1, 1.f / NQ,
        tmp2, sum2, sq2, NQ, C2, C2);

    // 7) final BN+ReLU -> out (BN params computed in-block)
    final_k<<<512, 256>>>(g2, beta2, out);
}

// round 15
// speedup vs baseline: 1.4981x; 1.0914x over previous
#include <cuda_runtime.h>
#include <cuda_bf16.h>
#include <math.h>
#include <stdint.h>

#define NREF 50000
#define NQ   25000
#define NE   400000
#define C0   128
#define C1   256
#define C2   256
#define BN_EPS 1e-5f

// ---------------- scratch (static device globals; no allocations) ----------------
__device__ float d_tmpF[NREF * C0];
__device__ float d_tmpS[NQ * C0];
__device__ float d_x0[NQ * C0];
__device__ float d_tmp1[NQ * C1];
__device__ float d_tmp2[NQ * C2];

__device__ float d_sumF[C0], d_sqF[C0], d_sumS[C0], d_sqS[C0];
__device__ float d_sum1[C1], d_sq1[C1], d_sum2[C2], d_sq2[C2];

__device__ int   d_cnt[NQ];
__device__ int   d_off[NQ + 1];
__device__ int   d_rank[NE];
__device__ int   d_er[NE];
__device__ float d_ew[NE];

// ---------------- warp MMA helpers (base-arch PTX, works on compute_103) ----------------
__device__ __forceinline__ void ldm4(uint32_t a[4], uint32_t addr) {
    asm volatile("ldmatrix.sync.aligned.m8n8.x4.shared.b16 {%0,%1,%2,%3}, [%4];"
        : "=r"(a[0]), "=r"(a[1]), "=r"(a[2]), "=r"(a[3]) : "r"(addr));
}
__device__ __forceinline__ void ldm4t(uint32_t a[4], uint32_t addr) {
    asm volatile("ldmatrix.sync.aligned.m8n8.x4.trans.shared.b16 {%0,%1,%2,%3}, [%4];"
        : "=r"(a[0]), "=r"(a[1]), "=r"(a[2]), "=r"(a[3]) : "r"(addr));
}
__device__ __forceinline__ void mma16816(float* d, const uint32_t a[4], uint32_t b0, uint32_t b1) {
    asm volatile("mma.sync.aligned.m16n8k16.row.col.f32.bf16.bf16.f32 "
        "{%0,%1,%2,%3}, {%4,%5,%6,%7}, {%8,%9}, {%0,%1,%2,%3};"
        : "+f"(d[0]), "+f"(d[1]), "+f"(d[2]), "+f"(d[3])
        : "r"(a[0]), "r"(a[1]), "r"(a[2]), "r"(a[3]), "r"(b0), "r"(b1));
}
__device__ __forceinline__ uint32_t pack_bf2(float x, float y) {
    __nv_bfloat162 t = __floats2bfloat162_rn(x, y);
    return *(uint32_t*)&t;
}
__device__ __forceinline__ void bsplit4(float4 v, uint32_t& h01, uint32_t& h23,
                                        uint32_t& l01, uint32_t& l23) {
    float hx = __bfloat162float(__float2bfloat16(v.x));
    float hy = __bfloat162float(__float2bfloat16(v.y));
    float hz = __bfloat162float(__float2bfloat16(v.z));
    float hw = __bfloat162float(__float2bfloat16(v.w));
    h01 = pack_bf2(hx, hy); h23 = pack_bf2(hz, hw);
    l01 = pack_bf2(v.x - hx, v.y - hy); l23 = pack_bf2(v.z - hz, v.w - hw);
}

// ---------------- zero init ----------------
__global__ void zero_k() {
    int i = blockIdx.x * blockDim.x + threadIdx.x;
    for (int t = i; t < NQ; t += gridDim.x * blockDim.x) d_cnt[t] = 0;
    if (i < C0) { d_sumF[i] = 0.f; d_sqF[i] = 0.f; d_sumS[i] = 0.f; d_sqS[i] = 0.f; }
    if (i < C1) { d_sum1[i] = 0.f; d_sq1[i] = 0.f; }
    if (i < C2) { d_sum2[i] = 0.f; d_sq2[i] = 0.f; }
}

// ---------------- tensor-core GEMM (mma.sync bf16 hi/lo), double-buffered -------------
// C[M,N] = f(A)[M,K] @ B[K,N] (+bias).  If bnG != null: f(v,k)=relu(v*a[k]+b[k]),
// (a,b) computed in-block from (bnSum,bnSq,bnG,bnBeta,bnInv).
// CTA 128x128, 256 threads = 8 warps (4x2). K chunked by 32, 2 smem stages:
// per chunk ONE __syncthreads(); convert(c+1) and MMA(c) issue between the same
// sync pair so tensor/LSU/FMA pipes overlap.
// Accuracy: D += Ahi*Bhi + Ahi*Blo + Alo*Bhi (lo*lo dropped).
#define SA 40
#define SB 136
#define A_STG_B (128 * SA * 2)          // 10240 B per A half-tile
#define B_STG_B (32 * SB * 2)           // 8704 B per B half-tile
#define A_STAGE (2 * A_STG_B)           // hi+lo = 20480
#define B_STAGE (2 * B_STG_B)           // hi+lo = 17408
#define B_BASE  (2 * A_STAGE)           // 40960
#define SSUM_OFF (B_BASE + 2 * B_STAGE) // 75776
#define SSQ_OFF  (SSUM_OFF + 512)
#define ASM_OFF  (SSQ_OFF + 512)
#define BSM_OFF  (ASM_OFF + 1024)
#define SMEM_TOT (BSM_OFF + 1024)       // 78848

__global__ void __launch_bounds__(256) mmagemm(
    const float* __restrict__ A, const float* __restrict__ B,
    const float* __restrict__ bias,
    const float* __restrict__ bnSum, const float* __restrict__ bnSq,
    const float* __restrict__ bnG, const float* __restrict__ bnBeta, float bnInv,
    float* __restrict__ C,
    float* __restrict__ gsum, float* __restrict__ gsq,
    int M, int K, int N)
{
    extern __shared__ char smemraw[];
    float* sSum = (float*)(smemraw + SSUM_OFF);
    float* sSq  = (float*)(smemraw + SSQ_OFF);
    float* aSm  = (float*)(smemraw + ASM_OFF);
    float* bSm  = (float*)(smemraw + BSM_OFF);
    const uint32_t sbase = (uint32_t)__cvta_generic_to_shared(smemraw);

    const int tid  = threadIdx.x;
    const int lane = tid & 31;
    const int warp = tid >> 5;
    const int wr = warp >> 1;
    const int wc = warp & 1;
    const int row0 = blockIdx.x * 128;
    const int col0 = blockIdx.y * 128;

    if (tid < 128) { sSum[tid] = 0.f; sSq[tid] = 0.f; }
    if (bnG && tid < K) {
        float m = bnSum[tid] * bnInv;
        float vv = bnSq[tid] * bnInv - m * m;
        float s = bnG[tid] * rsqrtf(vv + BN_EPS);
        aSm[tid] = s;
        bSm[tid] = bnBeta[tid] - m * s;
    }
    __syncthreads();   // aSm/bSm + sSum visible before any convert / epilogue

    float acc[2][8][4];
#pragma unroll
    for (int i = 0; i < 2; i++)
#pragma unroll
        for (int j = 0; j < 8; j++)
#pragma unroll
            for (int t = 0; t < 4; t++) acc[i][j][t] = 0.f;

    const int ar = tid >> 1;
    const int ac = (tid & 1) * 16;
    const int br = tid >> 3;
    const int bc = (tid & 7) * 16;
    const int gr_a = row0 + ar;
    const bool aval = gr_a < M;
    const float* Arow = A + (size_t)gr_a * K + ac;
    const bool doBN = (bnG != nullptr);

    const int nChunks = K / 32;

    // convert a chunk into stage s
    auto convert = [&](int k0, int s) {
        char* pAhi = smemraw + s * A_STAGE;
        char* pAlo = pAhi + A_STG_B;
        char* pBhi = smemraw + B_BASE + s * B_STAGE;
        char* pBlo = pBhi + B_STG_B;
#pragma unroll
        for (int h = 0; h < 4; h++) {
            int c = ac + h * 4;
            float4 v = aval ? *(const float4*)(Arow + k0 + h * 4)
                            : make_float4(0.f, 0.f, 0.f, 0.f);
            if (doBN) {
                int kb = k0 + c;
                v.x = fmaxf(fmaf(v.x, aSm[kb + 0], bSm[kb + 0]), 0.f);
                v.y = fmaxf(fmaf(v.y, aSm[kb + 1], bSm[kb + 1]), 0.f);
                v.z = fmaxf(fmaf(v.z, aSm[kb + 2], bSm[kb + 2]), 0.f);
                v.w = fmaxf(fmaf(v.w, aSm[kb + 3], bSm[kb + 3]), 0.f);
            }
            uint32_t h01, h23, l01, l23;
            bsplit4(v, h01, h23, l01, l23);
            int base = (ar * SA + c) * 2;
            *(uint32_t*)(pAhi + base)     = h01;
            *(uint32_t*)(pAhi + base + 4) = h23;
            *(uint32_t*)(pAlo + base)     = l01;
            *(uint32_t*)(pAlo + base + 4) = l23;
        }
#pragma unroll
        for (int h = 0; h < 4; h++) {
            int c = bc + h * 4;
            float4 v = *(const float4*)(B + (size_t)(k0 + br) * N + col0 + c);
            uint32_t h01, h23, l01, l23;
            bsplit4(v, h01, h23, l01, l23);
            int base = (br * SB + c) * 2;
            *(uint32_t*)(pBhi + base)     = h01;
            *(uint32_t*)(pBhi + base + 4) = h23;
            *(uint32_t*)(pBlo + base)     = l01;
            *(uint32_t*)(pBlo + base + 4) = l23;
        }
    };

    convert(0, 0);   // prologue: chunk 0 -> stage 0

    for (int chunk = 0; chunk < nChunks; chunk++) {
        const int s = chunk & 1;
        __syncthreads();   // stage s ready for MMA; stage s^1 free (MMA of chunk-1 done)

        if (chunk + 1 < nChunks) convert((chunk + 1) * 32, s ^ 1);

        const uint32_t ash = sbase + s * A_STAGE;
        const uint32_t asl = ash + A_STG_B;
        const uint32_t bsh = sbase + B_BASE + s * B_STAGE;
        const uint32_t bsl = bsh + B_STG_B;

#pragma unroll
        for (int kk = 0; kk < 32; kk += 16) {
            uint32_t ah[2][4], al[2][4];
            int arow = lane & 15;
            int acol = kk + ((lane >> 4) << 3);
#pragma unroll
            for (int i = 0; i < 2; i++) {
                int r = wr * 32 + i * 16 + arow;
                uint32_t off = (uint32_t)(r * SA + acol) * 2;
                ldm4(ah[i], ash + off);
                ldm4(al[i], asl + off);
            }
            int brow = kk + (lane & 15);
            int bcol = wc * 64 + ((lane >> 4) << 3);
#pragma unroll
            for (int g = 0; g < 4; g++) {
                uint32_t bh[4], bl[4];
                uint32_t off = (uint32_t)(brow * SB + bcol + g * 16) * 2;
                ldm4t(bh, bsh + off);
                ldm4t(bl, bsl + off);
#pragma unroll
                for (int i = 0; i < 2; i++) {
                    mma16816(acc[i][2 * g],     ah[i], bh[0], bh[1]);
                    mma16816(acc[i][2 * g],     ah[i], bl[0], bl[1]);
                    mma16816(acc[i][2 * g],     al[i], bh[0], bh[1]);
                    mma16816(acc[i][2 * g + 1], ah[i], bh[2], bh[3]);
                    mma16816(acc[i][2 * g + 1], ah[i], bl[2], bl[3]);
                    mma16816(acc[i][2 * g + 1], al[i], bh[2], bh[3]);
                }
            }
        }
    }

    // ---------------- epilogue: bias, store, BN stats ----------------
    const int qrow = lane >> 2;
    const int cpo  = (lane & 3) * 2;
#pragma unroll
    for (int j = 0; j < 8; j++) {
        int cl = wc * 64 + j * 8 + cpo;
        int gc = col0 + cl;
        float bx = 0.f, by = 0.f;
        if (bias) { bx = bias[gc]; by = bias[gc + 1]; }
        float se = 0.f, so = 0.f, qe = 0.f, qo = 0.f;
#pragma unroll
        for (int i = 0; i < 2; i++) {
            int r0r = row0 + wr * 32 + i * 16 + qrow;
            int r1r = r0r + 8;
            float d0 = acc[i][j][0] + bx, d1 = acc[i][j][1] + by;
            float d2 = acc[i][j][2] + bx, d3 = acc[i][j][3] + by;
            if (r0r < M) {
                *(float2*)(C + (size_t)r0r * N + gc) = make_float2(d0, d1);
                se += d0; so += d1; qe += d0 * d0; qo += d1 * d1;
            }
            if (r1r < M) {
                *(float2*)(C + (size_t)r1r * N + gc) = make_float2(d2, d3);
                se += d2; so += d3; qe += d2 * d2; qo += d3 * d3;
            }
        }
#pragma unroll
        for (int m = 4; m <= 16; m <<= 1) {
            se += __shfl_xor_sync(0xFFFFFFFFu, se, m);
            so += __shfl_xor_sync(0xFFFFFFFFu, so, m);
            qe += __shfl_xor_sync(0xFFFFFFFFu, qe, m);
            qo += __shfl_xor_sync(0xFFFFFFFFu, qo, m);
        }
        if (lane < 4) {
            atomicAdd(&sSum[cl], se);
            atomicAdd(&sSum[cl + 1], so);
            atomicAdd(&sSq[cl], qe);
            atomicAdd(&sSq[cl + 1], qo);
        }
    }
    __syncthreads();
    if (tid < 128) {
        atomicAdd(&gsum[col0 + tid], sSum[tid]);
        atomicAdd(&gsq[col0 + tid],  sSq[tid]);
    }
}

// ---------------- edge CSR build ----------------
// hist also records each edge's rank within its query -> scatter needs no atomics
__global__ void hist_k(const int* __restrict__ eq) {
    for (int i = blockIdx.x * blockDim.x + threadIdx.x; i < NE; i += gridDim.x * blockDim.x)
        d_rank[i] = atomicAdd(&d_cnt[eq[i]], 1);
}

#define SCAN_PER ((NQ + 1023) / 1024)
__global__ void __launch_bounds__(1024) scan_k() {
    __shared__ int sh[1024];
    const int t = threadIdx.x;
    const int base = t * SCAN_PER;
    int v[SCAN_PER];
    int s = 0;
#pragma unroll
    for (int j = 0; j < SCAN_PER; j++) {
        int i = base + j;
        int c = (i < NQ) ? d_cnt[i] : 0;
        v[j] = s;
        s += c;
    }
    sh[t] = s;
    __syncthreads();
    for (int d = 1; d < 1024; d <<= 1) {
        int x = (t >= d) ? sh[t - d] : 0;
        __syncthreads();
        sh[t] += x;
        __syncthreads();
    }
    int excl = sh[t] - s;
#pragma unroll
    for (int j = 0; j < SCAN_PER; j++) {
        int i = base + j;
        if (i < NQ) d_off[i] = excl + v[j];
    }
    if (t == 1023) d_off[NQ] = sh[1023];
}

__global__ void scatter_k(const float* __restrict__ refb, const float* __restrict__ qb,
                          const int* __restrict__ er, const int* __restrict__ eq) {
    for (int i = blockIdx.x * blockDim.x + threadIdx.x; i < NE; i += gridDim.x * blockDim.x) {
        int r = er[i], q = eq[i];
        float dx = refb[r * 4 + 1] - qb[q * 4 + 1];
        float dy = refb[r * 4 + 2] - qb[q * 4 + 2];
        float dz = refb[r * 4 + 3] - qb[q * 4 + 3];
        float dist = sqrtf(dx * dx + dy * dy + dz * dz);
        float w = 1.f / (dist + 1e-8f);
        int pos = d_off[q] + d_rank[i];
        d_er[pos] = r;
        d_ew[pos] = w;
    }
}

// ---------------- per-query gather + inline BN + skip + relu -> x0 ----------------
__global__ void __launch_bounds__(256) gather_k(
    const float* __restrict__ gf0, const float* __restrict__ bf0,
    const float* __restrict__ gs0, const float* __restrict__ bs0)
{
    __shared__ float aFs[C0], bFs[C0], aSs[C0], bSs[C0];
    const int tid = threadIdx.x;

    if (tid < 128) {
        float m = d_sumF[tid] * (1.f / NREF);
        float vv = d_sqF[tid] * (1.f / NREF) - m * m;
        float s = gf0[tid] * rsqrtf(vv + BN_EPS);
        aFs[tid] = s;
        bFs[tid] = bf0[tid] - m * s;
    } else {
        int c = tid - 128;
        float m = d_sumS[c] * (1.f / NQ);
        float vv = d_sqS[c] * (1.f / NQ) - m * m;
        float s = gs0[c] * rsqrtf(vv + BN_EPS);
        aSs[c] = s;
        bSs[c] = bs0[c] - m * s;
    }
    __syncthreads();

    int gwarp = (blockIdx.x * blockDim.x + tid) >> 5;
    int lane  = tid & 31;
    if (gwarp >= NQ) return;
    int beg = d_off[gwarp], end = d_off[gwarp + 1];

    float ws = 0.f;
    for (int p = beg + lane; p < end; p += 32) ws += d_ew[p];
#pragma unroll
    for (int s = 16; s; s >>= 1) ws += __shfl_xor_sync(0xFFFFFFFFu, ws, s);
    float inv = (end > beg) ? 1.f / ws : 0.f;

    const float4* F4 = (const float4*)d_tmpF;
    float4 acc = make_float4(0.f, 0.f, 0.f, 0.f);

    int p = beg;
    for (; p + 4 <= end; p += 4) {
        int r0 = d_er[p], r1 = d_er[p + 1], r2 = d_er[p + 2], r3 = d_er[p + 3];
        float w0 = d_ew[p] * inv, w1 = d_ew[p + 1] * inv, w2 = d_ew[p + 2] * inv, w3 = d_ew[p + 3] * inv;
        float4 f0 = F4[(size_t)r0 * 32 + lane];
        float4 f1 = F4[(size_t)r1 * 32 + lane];
        float4 f2 = F4[(size_t)r2 * 32 + lane];
        float4 f3 = F4[(size_t)r3 * 32 + lane];
        acc.x += w0 * f0.x + w1 * f1.x + w2 * f2.x + w3 * f3.x;
        acc.y += w0 * f0.y + w1 * f1.y + w2 * f2.y + w3 * f3.y;
        acc.z += w0 * f0.z + w1 * f1.z + w2 * f2.z + w3 * f3.z;
        acc.w += w0 * f0.w + w1 * f1.w + w2 * f2.w + w3 * f3.w;
    }
    for (; p < end; p++) {
        int r = d_er[p];
        float w = d_ew[p] * inv;
        float4 f = F4[(size_t)r * 32 + lane];
        acc.x += w * f.x; acc.y += w * f.y; acc.z += w * f.z; acc.w += w * f.w;
    }

    float4 aF = ((const float4*)aFs)[lane];
    float4 bF = ((const float4*)bFs)[lane];
    float4 aS = ((const float4*)aSs)[lane];
    float4 bS = ((const float4*)bSs)[lane];
    float4 sk = ((const float4*)d_tmpS)[(size_t)gwarp * 32 + lane];
    float he = (end > beg) ? 1.f : 0.f;

    float4 x;
    x.x = fmaxf(aF.x * acc.x + bF.x * he + aS.x * sk.x + bS.x, 0.f);
    x.y = fmaxf(aF.y * acc.y + bF.y * he + aS.y * sk.y + bS.y, 0.f);
    x.z = fmaxf(aF.z * acc.z + bF.z * he + aS.z * sk.z + bS.z, 0.f);
    x.w = fmaxf(aF.w * acc.w + bF.w * he + aS.w * sk.w + bS.w, 0.f);
    ((float4*)d_x0)[(size_t)gwarp * 32 + lane] = x;
}

// ---------------- final BN+ReLU on tmp2 -> out ----------------
__global__ void __launch_bounds__(256) final_k(
    const float* __restrict__ g2, const float* __restrict__ beta2, float* __restrict__ out)
{
    __shared__ float a2s[C2], b2s[C2];
    const int tid = threadIdx.x;
    {
        float m = d_sum2[tid] * (1.f / NQ);
        float vv = d_sq2[tid] * (1.f / NQ) - m * m;
        float s = g2[tid] * rsqrtf(vv + BN_EPS);
        a2s[tid] = s;
        b2s[tid] = beta2[tid] - m * s;
    }
    __syncthreads();

    const float4* T = (const float4*)d_tmp2;
    const float4* A = (const float4*)a2s;
    const float4* B = (const float4*)b2s;
    int total4 = NQ * C2 / 4;
    for (int i = blockIdx.x * blockDim.x + tid; i < total4; i += gridDim.x * blockDim.x) {
        float4 v = T[i];
        int c4 = i & (C2 / 4 - 1);
        float4 a = A[c4], b = B[c4];
        float4 o;
        o.x = fmaxf(fmaf(a.x, v.x, b.x), 0.f);
        o.y = fmaxf(fmaf(a.y, v.y, b.y), 0.f);
        o.z = fmaxf(fmaf(a.z, v.z, b.z), 0.f);
        o.w = fmaxf(fmaf(a.w, v.w, b.w), 0.f);
        ((float4*)out)[i] = o;
    }
}

// ---------------- host launch ----------------
extern "C" void kernel_launch(void* const* d_in, const int* in_sizes, int n_in,
                              void* d_out, int out_size)
{
    const float* ref_bxyz   = (const float*)d_in[0];
    const float* ref_feat   = (const float*)d_in[1];
    const float* query_bxyz = (const float*)d_in[2];
    const float* query_feat = (const float*)d_in[3];
    const int*   e_ref      = (const int*)d_in[4];
    const int*   e_query    = (const int*)d_in[5];
    const float* Wf0  = (const float*)d_in[6];
    const float* gf0  = (const float*)d_in[7];
    const float* bf0  = (const float*)d_in[8];
    const float* Ws0  = (const float*)d_in[9];
    const float* gs0  = (const float*)d_in[10];
    const float* bs0  = (const float*)d_in[11];
    const float* W1   = (const float*)d_in[12];
    const float* b1   = (const float*)d_in[13];
    const float* g1   = (const float*)d_in[14];
    const float* beta1= (const float*)d_in[15];
    const float* W2   = (const float*)d_in[16];
    const float* b2   = (const float*)d_in[17];
    const float* g2   = (const float*)d_in[18];
    const float* beta2= (const float*)d_in[19];
    float* out = (float*)d_out;

    float *tmpF, *tmpS, *x0, *tmp1, *tmp2;
    float *sumF, *sqF, *sumS, *sqS, *sum1, *sq1, *sum2, *sq2;
    cudaGetSymbolAddress((void**)&tmpF, d_tmpF);
    cudaGetSymbolAddress((void**)&tmpS, d_tmpS);
    cudaGetSymbolAddress((void**)&x0,   d_x0);
    cudaGetSymbolAddress((void**)&tmp1, d_tmp1);
    cudaGetSymbolAddress((void**)&tmp2, d_tmp2);
    cudaGetSymbolAddress((void**)&sumF, d_sumF);
    cudaGetSymbolAddress((void**)&sqF,  d_sqF);
    cudaGetSymbolAddress((void**)&sumS, d_sumS);
    cudaGetSymbolAddress((void**)&sqS,  d_sqS);
    cudaGetSymbolAddress((void**)&sum1, d_sum1);
    cudaGetSymbolAddress((void**)&sq1,  d_sq1);
    cudaGetSymbolAddress((void**)&sum2, d_sum2);
    cudaGetSymbolAddress((void**)&sq2,  d_sq2);

    cudaFuncSetAttribute(mmagemm, cudaFuncAttributeMaxDynamicSharedMemorySize, SMEM_TOT);

    // 0) zero counters + stats
    zero_k<<<128, 256>>>();

    // 1) CSR build + edge weights
    hist_k<<<1024, 256>>>(e_query);
    scan_k<<<1, 1024>>>();
    scatter_k<<<1024, 256>>>(ref_bxyz, query_bxyz, e_ref, e_query);

    // 2) GEMM F: ref_feat @ Wf0 -> tmpF  (M=50000, K=128, N=128)
    mmagemm<<<dim3((NREF + 127) / 128, 1), 256, SMEM_TOT>>>(
        ref_feat, Wf0, nullptr,
        nullptr, nullptr, nullptr, nullptr, 0.f,
        tmpF, sumF, sqF, NREF, C0, C0);

    // 3) GEMM S: query_feat @ Ws0 -> tmpS
    mmagemm<<<dim3((NQ + 127) / 128, 1), 256, SMEM_TOT>>>(
        query_feat, Ws0, nullptr,
        nullptr, nullptr, nullptr, nullptr, 0.f,
        tmpS, sumS, sqS, NQ, C0, C0);

    // 4) per-query gather -> x0
    gather_k<<<(NQ * 32 + 255) / 256, 256>>>(gf0, bf0, gs0, bs0);

    // 5) GEMM 1: x0 @ W1 + b1 -> tmp1 (M=25000, K=128, N=256)
    mmagemm<<<dim3((NQ + 127) / 128, 2), 256, SMEM_TOT>>>(
        x0, W1, b1,
        nullptr, nullptr, nullptr, nullptr, 0.f,
        tmp1, sum1, sq1, NQ, C0, C1);

    // 6) GEMM 2: bnrelu(tmp1) @ W2 + b2 -> tmp2 (K=256, N=256; BN in-block)
    mmagemm<<<dim3((NQ + 127) / 128, 2), 256, SMEM_TOT>>>(
        tmp1, W2, b2,
        sum1, sq1, g1, beta1, 1.f / NQ,
        tmp2, sum2, sq2, NQ, C2, C2);

    // 7) final BN+ReLU -> out
    final_k<<<512, 256>>>(g2, beta2, out);
}